// round 8
// baseline (speedup 1.0000x reference)
#include <cuda_runtime.h>
#include <cuda_bf16.h>
#include <float.h>

// PlanPredCollisionLoss: B=128, A=1024, M=6, T=16
// inputs: [0] ego_plan [B,T,2] f32
//         [1] agent_fut_preds [B,A,M,T,2] f32
//         [2] agent_score_preds [B,A,M] f32
//         [3] ego_plan_mask [B,T] f32
// output: scalar f32 mean loss

#define BB 128
#define AA 1024
#define MM 6
#define TT 16
#define NWARP 32          /* 1024 threads */

#define AGENT_THRESH 0.5f
#define X_DIS_THRESH 1.5f
#define Y_DIS_THRESH 3.0f
#define DIS2_THRESH  9.0f   /* DIS_THRESH^2, avoids sqrt */

// cross-block state; g_partial fully overwritten each launch, g_count returns
// to 0 at the end of every launch (last block resets it) -> graph-replay safe.
__device__ float    g_partial[BB];
__device__ unsigned g_count;

__global__ void __launch_bounds__(1024) ppcl_kernel(
    const float* __restrict__ ego,    // [B,T,2]
    const float* __restrict__ fut,    // [B,A,M,T,2]
    const float* __restrict__ sc,     // [B,A,M]
    const float* __restrict__ mask,   // [B,T]
    float* __restrict__ out)
{
    const int b    = blockIdx.x;
    const int tid  = threadIdx.x;
    const int warp = tid >> 5;
    const int lane = tid & 31;
    const int t    = lane & 15;

    __shared__ float s_rx[NWARP][TT];
    __shared__ float s_ry[NWARP][TT];

    // ego point for this lane's timestep (one 128B broadcast line)
    const float2 e = reinterpret_cast<const float2*>(ego + b * TT * 2)[t];

    // ---- per-lane argmax over M=6 modes for agent a = warp*32 + lane ----
    const int a = warp * 32 + lane;
    const float2* s2 = reinterpret_cast<const float2*>(
        sc + ((size_t)b * AA + a) * MM);           // 24B stride, 8B aligned
    const float2 p0 = s2[0], p1 = s2[1], p2 = s2[2];
    float smax = p0.x; int bm = 0;
    if (p0.y > smax) { smax = p0.y; bm = 1; }
    if (p1.x > smax) { smax = p1.x; bm = 2; }
    if (p1.y > smax) { smax = p1.y; bm = 3; }
    if (p2.x > smax) { smax = p2.x; bm = 4; }
    if (p2.y > smax) { smax = p2.y; bm = 5; }
    const int packed = (((a * MM + bm) * (TT * 2)) << 1) |
                       ((smax < AGENT_THRESH) ? 1 : 0);

    // ---- warp-autonomous min over this warp's 32 agents ----
    // iter i: lanes 0-15 handle agent 2i (t=lane), lanes 16-31 agent 2i+1.
    const float* fut_b = fut + (size_t)b * AA * MM * (TT * 2);
    const int half = lane >> 4;

    float xm = FLT_MAX, ym = FLT_MAX;
#pragma unroll
    for (int i = 0; i < 16; i++) {
        const int pk = __shfl_sync(0xFFFFFFFFu, packed, 2 * i + half);
        const float2 p = *reinterpret_cast<const float2*>(
            fut_b + (pk >> 1) + 2 * t);
        const float dx = e.x - p.x;
        const float dy = e.y - p.y;
        const float d2 = dx * dx + dy * dy;
        const float pen = (d2 > DIS2_THRESH || (pk & 1)) ? 100.0f : 0.0f;
        xm = fminf(xm, fabsf(dx) + pen);
        ym = fminf(ym, fabsf(dy) + pen);
    }
    // combine the two half-warps (same t)
    xm = fminf(xm, __shfl_xor_sync(0xFFFFFFFFu, xm, 16));
    ym = fminf(ym, __shfl_xor_sync(0xFFFFFFFFu, ym, 16));
    if (lane < 16) { s_rx[warp][lane] = xm; s_ry[warp][lane] = ym; }
    __syncthreads();

    // ---- block tail: warp 0. lanes 0-15 reduce x, lanes 16-31 reduce y ----
    if (warp == 0) {
        float mv;
        if (lane < 16) {
            mv = s_rx[0][t];
#pragma unroll
            for (int w = 1; w < NWARP; w++) mv = fminf(mv, s_rx[w][t]);
        } else {
            mv = s_ry[0][t];
#pragma unroll
            for (int w = 1; w < NWARP; w++) mv = fminf(mv, s_ry[w][t]);
        }
        const float thr = (lane < 16) ? X_DIS_THRESH : Y_DIS_THRESH;
        const float l_  = (mv <= thr) ? (thr - mv) : 0.0f;
        float v = l_ * mask[b * TT + t];
#pragma unroll
        for (int off = 16; off > 0; off >>= 1)
            v += __shfl_xor_sync(0xFFFFFFFFu, v, off);

        unsigned cnt = 0;
        if (lane == 0) {
            g_partial[b] = v;
            __threadfence();
            cnt = atomicAdd(&g_count, 1u) + 1u;
        }
        cnt = __shfl_sync(0xFFFFFFFFu, cnt, 0);

        if (cnt == BB) {
            // last block: 32 lanes sum 4 partials each (fixed order -> deterministic)
            __threadfence();
            const volatile float* gp = g_partial;
            float s = gp[lane * 4] + gp[lane * 4 + 1]
                    + gp[lane * 4 + 2] + gp[lane * 4 + 3];
#pragma unroll
            for (int off = 16; off > 0; off >>= 1)
                s += __shfl_xor_sync(0xFFFFFFFFu, s, off);
            if (lane == 0) {
                out[0] = s * (1.0f / (float)(BB * TT * 2));  // LOSS_WEIGHT=1
                g_count = 0;                                  // reset for replay
                __threadfence();
            }
        }
    }
}

extern "C" void kernel_launch(void* const* d_in, const int* in_sizes, int n_in,
                              void* d_out, int out_size) {
    const float* ego  = (const float*)d_in[0];
    const float* fut  = (const float*)d_in[1];
    const float* sc   = (const float*)d_in[2];
    const float* mask = (const float*)d_in[3];
    float* out = (float*)d_out;

    ppcl_kernel<<<BB, 1024>>>(ego, fut, sc, mask, out);
}